// round 7
// baseline (speedup 1.0000x reference)
#include <cuda_runtime.h>
#include <cuda_bf16.h>
#include <math.h>

#define Bn 32
#define Tn 384
#define Dn 768
#define D3 2304
#define NB 128
#define CPB 6      // columns per GRU block
#define RPB 18     // rows of w_hh per block (3 gates x CPB)
#define THRESH 0.95f

__device__ float g_xp[(size_t)Bn * Tn * D3];
__device__ float g_states[(size_t)Bn * Tn * Dn];
__device__ float g_h[2][Bn][Dn];
__device__ float g_probs[Bn * Tn];
__device__ float g_weights[Bn * Tn];
__device__ int   g_segend[Bn * Tn];
__device__ int   g_nsegs[Bn];
__device__ volatile int g_flag[NB];
__device__ int   g_done;

// ============ Kernel 1: xp = emb[sent] @ w_ih^T + b_ih  (12288 x 2304 x 768)
// Double-buffered SMEM, one __syncthreads per k-tile, LDG overlapped with FMA.
#define BM 128
#define BN 128
#define BK 16
#define NKT (Dn / BK)

__global__ __launch_bounds__(256) void k_xp(const int* __restrict__ sent,
                                            const float* __restrict__ emb,
                                            const float* __restrict__ w_ih,
                                            const float* __restrict__ b_ih) {
    __shared__ float As[2][BK][BM + 4];
    __shared__ float Bs[2][BK][BN + 4];
    __shared__ int toks[BM];

    const int tid = threadIdx.x;
    const int bm = blockIdx.y * BM;
    const int bn = blockIdx.x * BN;
    const int tx = tid & 15;
    const int ty = tid >> 4;
    const int lm = tid >> 2;
    const int lk4 = tid & 3;

    if (tid < BM) toks[tid] = sent[bm + tid];
    __syncthreads();

    float acc[8][8];
#pragma unroll
    for (int i = 0; i < 8; i++)
#pragma unroll
        for (int j = 0; j < 8; j++) acc[i][j] = 0.f;

    float4 pa[2], pb[2];
    // preload tile 0
#pragma unroll
    for (int p = 0; p < 2; p++) {
        int m = lm + p * 64;
        pa[p] = *(const float4*)(emb + (size_t)toks[m] * Dn + lk4 * 4);
        pb[p] = *(const float4*)(w_ih + (size_t)(bn + m) * Dn + lk4 * 4);
    }
#pragma unroll
    for (int p = 0; p < 2; p++) {
        int m = lm + p * 64;
        As[0][lk4 * 4 + 0][m] = pa[p].x; As[0][lk4 * 4 + 1][m] = pa[p].y;
        As[0][lk4 * 4 + 2][m] = pa[p].z; As[0][lk4 * 4 + 3][m] = pa[p].w;
        Bs[0][lk4 * 4 + 0][m] = pb[p].x; Bs[0][lk4 * 4 + 1][m] = pb[p].y;
        Bs[0][lk4 * 4 + 2][m] = pb[p].z; Bs[0][lk4 * 4 + 3][m] = pb[p].w;
    }

    for (int it = 0; it < NKT; it++) {
        const int cb = it & 1;
        if (it + 1 < NKT) {
            int kt = (it + 1) * BK;
#pragma unroll
            for (int p = 0; p < 2; p++) {
                int m = lm + p * 64;
                pa[p] = *(const float4*)(emb + (size_t)toks[m] * Dn + kt + lk4 * 4);
                pb[p] = *(const float4*)(w_ih + (size_t)(bn + m) * Dn + kt + lk4 * 4);
            }
        }
        __syncthreads();
#pragma unroll
        for (int k = 0; k < BK; k++) {
            float4 a0 = *(const float4*)&As[cb][k][ty * 8];
            float4 a1 = *(const float4*)&As[cb][k][ty * 8 + 4];
            float4 b0 = *(const float4*)&Bs[cb][k][tx * 4];
            float4 b1 = *(const float4*)&Bs[cb][k][64 + tx * 4];
            float av[8] = {a0.x, a0.y, a0.z, a0.w, a1.x, a1.y, a1.z, a1.w};
            float bv[8] = {b0.x, b0.y, b0.z, b0.w, b1.x, b1.y, b1.z, b1.w};
#pragma unroll
            for (int i = 0; i < 8; i++)
#pragma unroll
                for (int j = 0; j < 8; j++) acc[i][j] += av[i] * bv[j];
        }
        if (it + 1 < NKT) {
            const int nb = (it + 1) & 1;
#pragma unroll
            for (int p = 0; p < 2; p++) {
                int m = lm + p * 64;
                As[nb][lk4 * 4 + 0][m] = pa[p].x; As[nb][lk4 * 4 + 1][m] = pa[p].y;
                As[nb][lk4 * 4 + 2][m] = pa[p].z; As[nb][lk4 * 4 + 3][m] = pa[p].w;
                Bs[nb][lk4 * 4 + 0][m] = pb[p].x; Bs[nb][lk4 * 4 + 1][m] = pb[p].y;
                Bs[nb][lk4 * 4 + 2][m] = pb[p].z; Bs[nb][lk4 * 4 + 3][m] = pb[p].w;
            }
        }
    }

    float4 bias0 = *(const float4*)&b_ih[bn + tx * 4];
    float4 bias1 = *(const float4*)&b_ih[bn + 64 + tx * 4];
#pragma unroll
    for (int i = 0; i < 8; i++) {
        int row = bm + ty * 8 + i;
        float* orow = g_xp + (size_t)row * D3 + bn;
        float4 v0 = {acc[i][0] + bias0.x, acc[i][1] + bias0.y,
                     acc[i][2] + bias0.z, acc[i][3] + bias0.w};
        float4 v1 = {acc[i][4] + bias1.x, acc[i][5] + bias1.y,
                     acc[i][6] + bias1.z, acc[i][7] + bias1.w};
        *(float4*)&orow[tx * 4] = v0;
        *(float4*)&orow[64 + tx * 4] = v1;
    }
}

// ============ Kernel 2: persistent GRU scan. 128 blocks x 6 columns.
// Per-warp producer waits: warp ks polls only blocks [16ks,16ks+16).
#define SM_WS (RPB * 772)
#define SM_HS (8 * 32 * 100)
#define SM_PART (8 * RPB * 33)
#define SMEM_GRU ((SM_WS + SM_HS + SM_PART) * 4)

__device__ __forceinline__ void gbar_full(int phase) {
    __syncthreads();
    if (threadIdx.x == 0) {
        __threadfence();
        g_flag[blockIdx.x] = phase;
    }
    if ((int)threadIdx.x < NB) {
        while (g_flag[threadIdx.x] < phase) {}
    }
    __threadfence();
    __syncthreads();
}

__global__ __launch_bounds__(256, 1) void k_gru(const float* __restrict__ w_hh,
                                                const float* __restrict__ b_hh) {
    extern __shared__ float sm[];
    float* w_s = sm;
    float* h_s = sm + SM_WS;
    float* part = sm + SM_WS + SM_HS;

    const int tid = threadIdx.x;
    const int bid = blockIdx.x;
    const int c0 = bid * CPB;

    // w_hh slice: local rows 0..5 = r-gate, 6..11 = z, 12..17 = n
    for (int i = tid; i < RPB * 192; i += 256) {
        int lr = i / 192, k4 = i - lr * 192;
        int gr = (lr < CPB) ? (c0 + lr)
               : (lr < 2 * CPB) ? (Dn + c0 + lr - CPB)
                                : (2 * Dn + c0 + lr - 2 * CPB);
        *(float4*)(w_s + lr * 772 + k4 * 4) =
            *(const float4*)(w_hh + (size_t)gr * Dn + k4 * 4);
    }

    const int lane = tid & 31;
    const int ks = tid >> 5;      // warp = k-split chunk of 96

    const int gc = tid >> 5;      // gate-phase col 0..5 (tid<192)
    const int gb = lane;
    float br = 0.f, bz = 0.f, bnn = 0.f;
    if (tid < 192) {
        br = b_hh[c0 + gc];
        bz = b_hh[Dn + c0 + gc];
        bnn = b_hh[2 * Dn + c0 + gc];
    }
    // gate thread's own column within the staged h (for hold)
    const int hc = c0 + gc;
    const int hold_idx = (hc / 96) * 3200 + gb * 100 + (hc % 96);

    const int kb4 = ks * 24;
    float* hw = h_s + ks * 3200;  // this warp's staged h [32][100]

    // zero h parity 0 (NB*192 == Bn*Dn)
    if (tid < 192) (&g_h[0][0][0])[bid * 192 + tid] = 0.f;
    gbar_full(1);

    for (int t = 0; t < Tn; t++) {
        const int par = t & 1;

        float xr = 0.f, xz = 0.f, xn = 0.f;
        if (tid < 192) {
            size_t mrow = (size_t)(gb * Tn + t) * D3 + c0 + gc;
            xr = g_xp[mrow];
            xz = g_xp[mrow + Dn];
            xn = g_xp[mrow + 2 * Dn];
        }

        // per-warp producer wait: warp ks's h chunk is written by blocks
        // [16ks, 16ks+16). Wait only on those 16 flags, then stage.
        if (lane < 16) {
            while (g_flag[16 * ks + lane] < t + 1) {}
        }
        __syncwarp();

        const float4* gh4 = (const float4*)(&g_h[par][0][0]);  // [32][192] f4
#pragma unroll
        for (int i = 0; i < 24; i++) {
            int idx = i * 32 + lane;
            int row = idx / 24;
            int col = idx - row * 24;
            float4 v = __ldcv(gh4 + row * 192 + kb4 + col);
            *(float4*)(hw + row * 100 + col * 4) = v;
        }
        __syncwarp();

        float acc[RPB];
#pragma unroll
        for (int r = 0; r < RPB; r++) acc[r] = 0.f;

        const float* wb = w_s + ks * 96;
        const float* hb = hw + lane * 100;
#pragma unroll 2
        for (int k4 = 0; k4 < 24; k4++) {
            float4 hv = *(const float4*)(hb + k4 * 4);
#pragma unroll
            for (int r = 0; r < RPB; r++) {
                float4 wv = *(const float4*)(wb + r * 772 + k4 * 4);
                acc[r] += wv.x * hv.x + wv.y * hv.y + wv.z * hv.z + wv.w * hv.w;
            }
        }
#pragma unroll
        for (int r = 0; r < RPB; r++)
            part[ks * (RPB * 33) + r * 33 + lane] = acc[r];
        __syncthreads();

        if (tid < 192) {
            float hold = h_s[hold_idx];   // staged copy of h[par][gb][hc]
            float hr = br, hz = bz, hn = bnn;
#pragma unroll
            for (int s2 = 0; s2 < 8; s2++) {
                const float* pp = part + s2 * (RPB * 33);
                hr += pp[gc * 33 + gb];
                hz += pp[(CPB + gc) * 33 + gb];
                hn += pp[(2 * CPB + gc) * 33 + gb];
            }
            float r = 1.f / (1.f + expf(-(xr + hr)));
            float z = 1.f / (1.f + expf(-(xz + hz)));
            float n = tanhf(xn + r * hn);
            float hnew = (1.f - z) * n + z * hold;
            g_h[par ^ 1][gb][hc] = hnew;
            g_states[(size_t)(gb * Tn + t) * Dn + hc] = hnew;
            __threadfence();
        }
        __syncthreads();
        if (tid == 0) g_flag[bid] = t + 2;
    }

    // departure-counted barrier reset (safe for graph replay)
    if (tid == 0) {
        int old = atomicAdd(&g_done, 1);
        if (old == NB - 1) {
            for (int i = 0; i < NB; i++) g_flag[i] = 0;
            __threadfence();
            g_done = 0;
        }
    }
}

// ============ Kernel 3: probs = sigmoid(states @ w_act + b_act)
__global__ __launch_bounds__(256) void k_probs(const float* __restrict__ w_act,
                                               const float* __restrict__ b_act,
                                               float* __restrict__ out_probs) {
    int warp = threadIdx.x >> 5, lane = threadIdx.x & 31;
    int m = blockIdx.x * 8 + warp;
    const float4* row = (const float4*)(g_states + (size_t)m * Dn);
    const float4* wv = (const float4*)w_act;
    float acc = 0.f;
    for (int i = lane; i < 192; i += 32) {
        float4 v = row[i], w = wv[i];
        acc += v.x * w.x + v.y * w.y + v.z * w.z + v.w * w.w;
    }
#pragma unroll
    for (int off = 16; off; off >>= 1) acc += __shfl_down_sync(0xffffffffu, acc, off);
    if (lane == 0) {
        float p = 1.f / (1.f + expf(-(acc + b_act[0])));
        g_probs[m] = p;
        out_probs[m] = p;
    }
}

// ============ Kernel 4: ACT halting scan (probs staged in smem)
__global__ void k_halt() {
    extern __shared__ float ps[];
    int tid = threadIdx.x;
    for (int i = tid; i < Bn * Tn; i += 384) {
        int b = i / Tn, t = i - b * Tn;
        ps[b * (Tn + 1) + t] = g_probs[i];
    }
    __syncthreads();
    if (tid < Bn) {
        int b = tid;
        const float* pb = ps + b * (Tn + 1);
        float acc = 0.f;
        int ns = 0;
        for (int t = 0; t < Tn; t++) {
            float p = pb[t];
            float a = acc + p;
            if (a > THRESH) {
                g_weights[b * Tn + t] = p - (a - 1.f);
                g_segend[b * Tn + ns] = t;
                ns++;
                acc = 0.f;
            } else {
                g_weights[b * Tn + t] = p;
                acc = a;
            }
        }
        g_nsegs[b] = ns;
    }
}

// ============ Kernel 5: segment sums -> output embs (zero-padded)
__global__ __launch_bounds__(128) void k_out(float* __restrict__ out) {
    int bs = blockIdx.x;
    int b = bs / Tn, s = bs - b * Tn;
    float* o = out + (size_t)bs * Dn;
    int tid = threadIdx.x;
    if (s >= g_nsegs[b]) {
        for (int d = tid; d < Dn; d += 128) o[d] = 0.f;
        return;
    }
    int t1 = g_segend[b * Tn + s];
    int t0 = (s == 0) ? 0 : g_segend[b * Tn + s - 1] + 1;
    for (int d = tid; d < Dn; d += 128) {
        float sum = 0.f;
        for (int t = t0; t <= t1; t++)
            sum += g_states[(size_t)(b * Tn + t) * Dn + d] * g_weights[b * Tn + t];
        o[d] = sum;
    }
}

extern "C" void kernel_launch(void* const* d_in, const int* in_sizes, int n_in,
                              void* d_out, int out_size) {
    const int* sent    = (const int*)d_in[0];
    const float* emb   = (const float*)d_in[1];
    const float* w_ih  = (const float*)d_in[2];
    const float* w_hh  = (const float*)d_in[3];
    const float* b_ih  = (const float*)d_in[4];
    const float* b_hh  = (const float*)d_in[5];
    const float* w_act = (const float*)d_in[6];
    const float* b_act = (const float*)d_in[7];
    float* out = (float*)d_out;

    cudaFuncSetAttribute(k_gru, cudaFuncAttributeMaxDynamicSharedMemorySize, SMEM_GRU);
    cudaFuncSetAttribute(k_halt, cudaFuncAttributeMaxDynamicSharedMemorySize,
                         Bn * (Tn + 1) * 4);

    k_xp<<<dim3(D3 / BN, (Bn * Tn) / BM), 256>>>(sent, emb, w_ih, b_ih);
    k_gru<<<NB, 256, SMEM_GRU>>>(w_hh, b_hh);
    k_probs<<<(Bn * Tn) / 8, 256>>>(w_act, b_act, out + (size_t)Bn * Tn * Dn);
    k_halt<<<1, 384, Bn * (Tn + 1) * 4>>>();
    k_out<<<Bn * Tn, 128>>>(out);
}

// round 8
// speedup vs baseline: 1.1032x; 1.1032x over previous
#include <cuda_runtime.h>
#include <cuda_bf16.h>
#include <math.h>

#define Bn 32
#define Tn 384
#define Dn 768
#define D3 2304
#define NB 96
#define THRESH 0.95f

__device__ float g_xp[(size_t)Bn * Tn * D3];
__device__ float g_states[(size_t)Bn * Tn * Dn];
__device__ float g_h[2][Bn][Dn];
__device__ float g_probs[Bn * Tn];
__device__ float g_weights[Bn * Tn];
__device__ int   g_segend[Bn * Tn];
__device__ int   g_nsegs[Bn];
__device__ volatile int g_flag[NB];
__device__ int   g_done;

// bf16 hi/lo split planes
__device__ __nv_bfloat16 g_xh[(size_t)Bn * Tn * Dn];
__device__ __nv_bfloat16 g_xl[(size_t)Bn * Tn * Dn];
__device__ __nv_bfloat16 g_wh[(size_t)D3 * Dn];
__device__ __nv_bfloat16 g_wl[(size_t)D3 * Dn];

// ============ split kernels: x = emb[sent] (gather) -> bf16 hi/lo
__global__ __launch_bounds__(256) void k_split_x(const int* __restrict__ sent,
                                                 const float* __restrict__ emb) {
    int idx = blockIdx.x * 256 + threadIdx.x;     // over 12288*192 float4s
    int m = idx / 192, c4 = idx - (idx / 192) * 192;
    int tok = sent[m];
    float4 v = *(const float4*)(emb + (size_t)tok * Dn + c4 * 4);
    float hx = __bfloat162float(__float2bfloat16(v.x));
    float hy = __bfloat162float(__float2bfloat16(v.y));
    float hz = __bfloat162float(__float2bfloat16(v.z));
    float hw = __bfloat162float(__float2bfloat16(v.w));
    __nv_bfloat162 h0 = __floats2bfloat162_rn(hx, hy);
    __nv_bfloat162 h1 = __floats2bfloat162_rn(hz, hw);
    __nv_bfloat162 l0 = __floats2bfloat162_rn(v.x - hx, v.y - hy);
    __nv_bfloat162 l1 = __floats2bfloat162_rn(v.z - hz, v.w - hw);
    ((__nv_bfloat162*)g_xh)[m * 384 + c4 * 2] = h0;
    ((__nv_bfloat162*)g_xh)[m * 384 + c4 * 2 + 1] = h1;
    ((__nv_bfloat162*)g_xl)[m * 384 + c4 * 2] = l0;
    ((__nv_bfloat162*)g_xl)[m * 384 + c4 * 2 + 1] = l1;
}

__global__ __launch_bounds__(256) void k_split_w(const float* __restrict__ w_ih) {
    int idx = blockIdx.x * 256 + threadIdx.x;     // over 2304*192 float4s
    float4 v = *(const float4*)(w_ih + (size_t)idx * 4);
    float hx = __bfloat162float(__float2bfloat16(v.x));
    float hy = __bfloat162float(__float2bfloat16(v.y));
    float hz = __bfloat162float(__float2bfloat16(v.z));
    float hw = __bfloat162float(__float2bfloat16(v.w));
    ((__nv_bfloat162*)g_wh)[idx * 2]     = __floats2bfloat162_rn(hx, hy);
    ((__nv_bfloat162*)g_wh)[idx * 2 + 1] = __floats2bfloat162_rn(hz, hw);
    ((__nv_bfloat162*)g_wl)[idx * 2]     = __floats2bfloat162_rn(v.x - hx, v.y - hy);
    ((__nv_bfloat162*)g_wl)[idx * 2 + 1] = __floats2bfloat162_rn(v.z - hz, v.w - hw);
}

// ============ Kernel 1: xp via mma.sync bf16 3-term split
// Block 128x128, 8 warps (2m x 4n), k16 double-buffered stages.
__device__ __forceinline__ void mma_bf16(float* c, const unsigned* a, const unsigned* b) {
    asm volatile(
        "mma.sync.aligned.m16n8k16.row.col.f32.bf16.bf16.f32 "
        "{%0,%1,%2,%3}, {%4,%5,%6,%7}, {%8,%9}, {%0,%1,%2,%3};"
        : "+f"(c[0]), "+f"(c[1]), "+f"(c[2]), "+f"(c[3])
        : "r"(a[0]), "r"(a[1]), "r"(a[2]), "r"(a[3]), "r"(b[0]), "r"(b[1]));
}

__global__ __launch_bounds__(256, 1) void k_xp_mma(const float* __restrict__ b_ih) {
    // SMEM fragment-permuted planes [buf][tile][lane][reg]
    __shared__ unsigned Ah[2][8][32][4];
    __shared__ unsigned Al[2][8][32][4];
    __shared__ unsigned Bh[2][16][32][2];
    __shared__ unsigned Bl[2][16][32][2];

    const int tid = threadIdx.x;
    const int bm = blockIdx.y * 128;
    const int bn = blockIdx.x * 128;
    const int warp = tid >> 5;
    const int lane = tid & 31;
    const int wm = warp >> 2;       // 0..1
    const int wn = warp & 3;        // 0..3
    const int gid = lane >> 2;
    const int tig = lane & 3;

    // loader identity: row = tid>>1, k8-half = tid&1
    const int lrow = tid >> 1;
    const int hs = tid & 1;
    const int lmt = lrow >> 4;        // A tile
    const int lnt = lrow >> 3;        // B tile
    const int lml = (lrow & 7) * 4;   // lane base
    const int lreg = (lrow >> 3) & 1; // A reg low bit

    const uint4* xh = (const uint4*)(g_xh + (size_t)(bm + lrow) * Dn + hs * 8);
    const uint4* xl = (const uint4*)(g_xl + (size_t)(bm + lrow) * Dn + hs * 8);
    const uint4* wh = (const uint4*)(g_wh + (size_t)(bn + lrow) * Dn + hs * 8);
    const uint4* wl = (const uint4*)(g_wl + (size_t)(bn + lrow) * Dn + hs * 8);
    // stride per k16 tile = 16 halves = 2 uint4 -> as uint4 ptr stride 2

    float acc[4][4][4];
#pragma unroll
    for (int i = 0; i < 4; i++)
#pragma unroll
        for (int j = 0; j < 4; j++)
#pragma unroll
            for (int r = 0; r < 4; r++) acc[i][j][r] = 0.f;

    // stage k-tile 0 into buf 0
    {
        uint4 va = xh[0], vb = xl[0], vc = wh[0], vd = wl[0];
        const unsigned* aw = (const unsigned*)&va;
        const unsigned* bw = (const unsigned*)&vb;
        const unsigned* cw = (const unsigned*)&vc;
        const unsigned* dw = (const unsigned*)&vd;
#pragma unroll
        for (int j = 0; j < 4; j++) {
            Ah[0][lmt][lml + j][lreg + 2 * hs] = aw[j];
            Al[0][lmt][lml + j][lreg + 2 * hs] = bw[j];
            Bh[0][lnt][lml + j][hs] = cw[j];
            Bl[0][lnt][lml + j][hs] = dw[j];
        }
    }

    for (int kt = 0; kt < 48; kt++) {
        const int cb = kt & 1;
        uint4 va, vb, vc, vd;
        if (kt + 1 < 48) {
            va = xh[(kt + 1) * 2]; vb = xl[(kt + 1) * 2];
            vc = wh[(kt + 1) * 2]; vd = wl[(kt + 1) * 2];
        }
        __syncthreads();

        unsigned ah[4][4], al[4][4], bh[4][2], bl[4][2];
#pragma unroll
        for (int i = 0; i < 4; i++) {
            *(uint4*)ah[i] = *(const uint4*)&Ah[cb][wm * 4 + i][lane][0];
            *(uint4*)al[i] = *(const uint4*)&Al[cb][wm * 4 + i][lane][0];
        }
#pragma unroll
        for (int j = 0; j < 4; j++) {
            *(uint2*)bh[j] = *(const uint2*)&Bh[cb][wn * 4 + j][lane][0];
            *(uint2*)bl[j] = *(const uint2*)&Bl[cb][wn * 4 + j][lane][0];
        }
#pragma unroll
        for (int i = 0; i < 4; i++)
#pragma unroll
            for (int j = 0; j < 4; j++) {
                mma_bf16(acc[i][j], ah[i], bh[j]);
                mma_bf16(acc[i][j], al[i], bh[j]);
                mma_bf16(acc[i][j], ah[i], bl[j]);
            }

        if (kt + 1 < 48) {
            const int nb = (kt + 1) & 1;
            const unsigned* aw = (const unsigned*)&va;
            const unsigned* bw = (const unsigned*)&vb;
            const unsigned* cw = (const unsigned*)&vc;
            const unsigned* dw = (const unsigned*)&vd;
#pragma unroll
            for (int j = 0; j < 4; j++) {
                Ah[nb][lmt][lml + j][lreg + 2 * hs] = aw[j];
                Al[nb][lmt][lml + j][lreg + 2 * hs] = bw[j];
                Bh[nb][lnt][lml + j][hs] = cw[j];
                Bl[nb][lnt][lml + j][hs] = dw[j];
            }
        }
    }

    // epilogue: c frag -> g_xp with bias
#pragma unroll
    for (int j = 0; j < 4; j++) {
        int ncol = bn + (wn * 4 + j) * 8 + 2 * tig;
        float2 bias = *(const float2*)&b_ih[ncol];
#pragma unroll
        for (int i = 0; i < 4; i++) {
            int m0 = bm + (wm * 4 + i) * 16 + gid;
            float2 v0 = {acc[i][j][0] + bias.x, acc[i][j][1] + bias.y};
            float2 v1 = {acc[i][j][2] + bias.x, acc[i][j][3] + bias.y};
            *(float2*)(g_xp + (size_t)m0 * D3 + ncol) = v0;
            *(float2*)(g_xp + (size_t)(m0 + 8) * D3 + ncol) = v1;
        }
    }
}

// ============ Kernel 2: persistent GRU scan (exact R3 version, NB=96)
#define CPB8 8
#define SM_WS (24 * 772)
#define SM_HS (8 * 32 * 100)
#define SM_PART (8 * 24 * 33)
#define SMEM_GRU ((SM_WS + SM_HS + SM_PART) * 4)

__device__ __forceinline__ void gbar(int phase) {
    __syncthreads();
    if (threadIdx.x == 0) {
        __threadfence();
        g_flag[blockIdx.x] = phase;
    }
    if ((int)threadIdx.x < NB) {
        while (g_flag[threadIdx.x] < phase) {}
    }
    __threadfence();
    __syncthreads();
}

__global__ __launch_bounds__(256, 1) void k_gru(const float* __restrict__ w_hh,
                                                const float* __restrict__ b_hh) {
    extern __shared__ float sm[];
    float* w_s = sm;
    float* h_s = sm + SM_WS;
    float* part = sm + SM_WS + SM_HS;

    const int tid = threadIdx.x;
    const int bid = blockIdx.x;
    const int c0 = bid * CPB8;

    for (int i = tid; i < 24 * 192; i += 256) {
        int lr = i / 192, k4 = i - lr * 192;
        int gr = (lr < 8) ? (c0 + lr) : (lr < 16) ? (Dn + c0 + lr - 8)
                                                  : (2 * Dn + c0 + lr - 16);
        *(float4*)(w_s + lr * 772 + k4 * 4) =
            *(const float4*)(w_hh + (size_t)gr * Dn + k4 * 4);
    }

    const int gc = tid >> 5;
    const int gb = tid & 31;
    const float br = b_hh[c0 + gc];
    const float bz = b_hh[Dn + c0 + gc];
    const float bnn = b_hh[2 * Dn + c0 + gc];

    const int lane = tid & 31;
    const int ks = tid >> 5;
    const int rp = lane >> 2;
    const int bp = lane & 3;
    const int kb4 = ks * 24;

    float* hw = h_s + ks * 3200;

    (&g_h[0][0][0])[bid * 256 + tid] = 0.f;
    gbar(1);

    for (int t = 0; t < Tn; t++) {
        const int par = t & 1;

        size_t mrow = (size_t)(gb * Tn + t) * D3 + c0 + gc;
        float xr = g_xp[mrow];
        float xz = g_xp[mrow + Dn];
        float xn = g_xp[mrow + 2 * Dn];

        const float4* gh4 = (const float4*)(&g_h[par][0][0]);
#pragma unroll
        for (int i = 0; i < 24; i++) {
            int idx = i * 32 + lane;
            int row = idx / 24;
            int col = idx - row * 24;
            float4 v = __ldcv(gh4 + row * 192 + kb4 + col);
            *(float4*)(hw + row * 100 + col * 4) = v;
        }
        __syncwarp();

        float acc[3][8];
#pragma unroll
        for (int i = 0; i < 3; i++)
#pragma unroll
            for (int j = 0; j < 8; j++) acc[i][j] = 0.f;

        const float* wb = w_s + (rp * 3) * 772 + ks * 96;
        const float* hbase = hw + bp * 100;
#pragma unroll 4
        for (int k4 = 0; k4 < 24; k4++) {
            float4 w0 = *(const float4*)(wb + k4 * 4);
            float4 w1 = *(const float4*)(wb + 772 + k4 * 4);
            float4 w2 = *(const float4*)(wb + 1544 + k4 * 4);
#pragma unroll
            for (int j = 0; j < 8; j++) {
                float4 hv = *(const float4*)(hbase + j * 400 + k4 * 4);
                acc[0][j] += w0.x * hv.x + w0.y * hv.y + w0.z * hv.z + w0.w * hv.w;
                acc[1][j] += w1.x * hv.x + w1.y * hv.y + w1.z * hv.z + w1.w * hv.w;
                acc[2][j] += w2.x * hv.x + w2.y * hv.y + w2.z * hv.z + w2.w * hv.w;
            }
        }
#pragma unroll
        for (int i = 0; i < 3; i++)
#pragma unroll
            for (int j = 0; j < 8; j++)
                part[ks * 792 + (rp * 3 + i) * 33 + (bp + 4 * j)] = acc[i][j];
        __syncthreads();

        float hold = __ldcv(&g_h[par][gb][c0 + gc]);
        float hr = br, hz = bz, hn = bnn;
#pragma unroll
        for (int s2 = 0; s2 < 8; s2++) {
            hr += part[s2 * 792 + gc * 33 + gb];
            hz += part[s2 * 792 + (8 + gc) * 33 + gb];
            hn += part[s2 * 792 + (16 + gc) * 33 + gb];
        }
        float r = 1.f / (1.f + expf(-(xr + hr)));
        float z = 1.f / (1.f + expf(-(xz + hz)));
        float n = tanhf(xn + r * hn);
        float hnew = (1.f - z) * n + z * hold;
        g_h[par ^ 1][gb][c0 + gc] = hnew;
        g_states[(size_t)(gb * Tn + t) * Dn + c0 + gc] = hnew;

        gbar(t + 2);
    }

    if (tid == 0) {
        int old = atomicAdd(&g_done, 1);
        if (old == NB - 1) {
            for (int i = 0; i < NB; i++) g_flag[i] = 0;
            __threadfence();
            g_done = 0;
        }
    }
}

// ============ Kernel 3: probs = sigmoid(states @ w_act + b_act)
__global__ __launch_bounds__(256) void k_probs(const float* __restrict__ w_act,
                                               const float* __restrict__ b_act,
                                               float* __restrict__ out_probs) {
    int warp = threadIdx.x >> 5, lane = threadIdx.x & 31;
    int m = blockIdx.x * 8 + warp;
    const float4* row = (const float4*)(g_states + (size_t)m * Dn);
    const float4* wv = (const float4*)w_act;
    float acc = 0.f;
    for (int i = lane; i < 192; i += 32) {
        float4 v = row[i], w = wv[i];
        acc += v.x * w.x + v.y * w.y + v.z * w.z + v.w * w.w;
    }
#pragma unroll
    for (int off = 16; off; off >>= 1) acc += __shfl_down_sync(0xffffffffu, acc, off);
    if (lane == 0) {
        float p = 1.f / (1.f + expf(-(acc + b_act[0])));
        g_probs[m] = p;
        out_probs[m] = p;
    }
}

// ============ Kernel 4: ACT halting scan
__global__ void k_halt() {
    extern __shared__ float ps[];
    int tid = threadIdx.x;
    for (int i = tid; i < Bn * Tn; i += 384) {
        int b = i / Tn, t = i - b * Tn;
        ps[b * (Tn + 1) + t] = g_probs[i];
    }
    __syncthreads();
    if (tid < Bn) {
        int b = tid;
        const float* pb = ps + b * (Tn + 1);
        float acc = 0.f;
        int ns = 0;
        for (int t = 0; t < Tn; t++) {
            float p = pb[t];
            float a = acc + p;
            if (a > THRESH) {
                g_weights[b * Tn + t] = p - (a - 1.f);
                g_segend[b * Tn + ns] = t;
                ns++;
                acc = 0.f;
            } else {
                g_weights[b * Tn + t] = p;
                acc = a;
            }
        }
        g_nsegs[b] = ns;
    }
}

// ============ Kernel 5: segment sums -> output embs
__global__ __launch_bounds__(128) void k_out(float* __restrict__ out) {
    int bs = blockIdx.x;
    int b = bs / Tn, s = bs - b * Tn;
    float* o = out + (size_t)bs * Dn;
    int tid = threadIdx.x;
    if (s >= g_nsegs[b]) {
        for (int d = tid; d < Dn; d += 128) o[d] = 0.f;
        return;
    }
    int t1 = g_segend[b * Tn + s];
    int t0 = (s == 0) ? 0 : g_segend[b * Tn + s - 1] + 1;
    for (int d = tid; d < Dn; d += 128) {
        float sum = 0.f;
        for (int t = t0; t <= t1; t++)
            sum += g_states[(size_t)(b * Tn + t) * Dn + d] * g_weights[b * Tn + t];
        o[d] = sum;
    }
}

extern "C" void kernel_launch(void* const* d_in, const int* in_sizes, int n_in,
                              void* d_out, int out_size) {
    const int* sent    = (const int*)d_in[0];
    const float* emb   = (const float*)d_in[1];
    const float* w_ih  = (const float*)d_in[2];
    const float* w_hh  = (const float*)d_in[3];
    const float* b_ih  = (const float*)d_in[4];
    const float* b_hh  = (const float*)d_in[5];
    const float* w_act = (const float*)d_in[6];
    const float* b_act = (const float*)d_in[7];
    float* out = (float*)d_out;

    cudaFuncSetAttribute(k_gru, cudaFuncAttributeMaxDynamicSharedMemorySize, SMEM_GRU);
    cudaFuncSetAttribute(k_halt, cudaFuncAttributeMaxDynamicSharedMemorySize,
                         Bn * (Tn + 1) * 4);

    k_split_x<<<(Bn * Tn * 192) / 256, 256>>>(sent, emb);
    k_split_w<<<(D3 * 192) / 256, 256>>>(w_ih);
    k_xp_mma<<<dim3(D3 / 128, (Bn * Tn) / 128), 256>>>(b_ih);
    k_gru<<<NB, 256, SMEM_GRU>>>(w_hh, b_hh);
    k_probs<<<(Bn * Tn) / 8, 256>>>(w_act, b_act, out + (size_t)Bn * Tn * Dn);
    k_halt<<<1, 384, Bn * (Tn + 1) * 4>>>();
    k_out<<<Bn * Tn, 128>>>(out);
}

// round 9
// speedup vs baseline: 1.2678x; 1.1492x over previous
#include <cuda_runtime.h>
#include <cuda_bf16.h>
#include <math.h>

#define Bn 32
#define Tn 384
#define Dn 768
#define D3 2304
#define NB 96
#define THRESH 0.95f

__device__ float g_xp[(size_t)Bn * Tn * D3];
__device__ float g_states[(size_t)Bn * Tn * Dn];
__device__ float g_probs[Bn * Tn];
__device__ float g_weights[Bn * Tn];
__device__ int   g_segend[Bn * Tn];
__device__ int   g_nsegs[Bn];
__device__ volatile int g_flag[NB];
__device__ int   g_done;

// h exchange in mma A-fragment layout: [par][mt 2][ktile 96][lane 32][reg 4]
#define HFP (2 * 96 * 128)
__device__ float g_hfrag[2 * HFP];
// w_hh fragment-permuted per block: [bid 96][ks 8][q 12][j 3][lane 32][4]
#define WFB (8 * 12 * 3 * 32 * 4)
__device__ float g_wfrag[(size_t)NB * WFB];

// bf16 hi/lo split planes for xp GEMM
__device__ __nv_bfloat16 g_xh[(size_t)Bn * Tn * Dn];
__device__ __nv_bfloat16 g_xl[(size_t)Bn * Tn * Dn];
__device__ __nv_bfloat16 g_wh[(size_t)D3 * Dn];
__device__ __nv_bfloat16 g_wl[(size_t)D3 * Dn];

// ============ split kernels for xp
__global__ __launch_bounds__(256) void k_split_x(const int* __restrict__ sent,
                                                 const float* __restrict__ emb) {
    int idx = blockIdx.x * 256 + threadIdx.x;
    int m = idx / 192, c4 = idx - (idx / 192) * 192;
    int tok = sent[m];
    float4 v = *(const float4*)(emb + (size_t)tok * Dn + c4 * 4);
    float hx = __bfloat162float(__float2bfloat16(v.x));
    float hy = __bfloat162float(__float2bfloat16(v.y));
    float hz = __bfloat162float(__float2bfloat16(v.z));
    float hw = __bfloat162float(__float2bfloat16(v.w));
    ((__nv_bfloat162*)g_xh)[m * 384 + c4 * 2]     = __floats2bfloat162_rn(hx, hy);
    ((__nv_bfloat162*)g_xh)[m * 384 + c4 * 2 + 1] = __floats2bfloat162_rn(hz, hw);
    ((__nv_bfloat162*)g_xl)[m * 384 + c4 * 2]     = __floats2bfloat162_rn(v.x - hx, v.y - hy);
    ((__nv_bfloat162*)g_xl)[m * 384 + c4 * 2 + 1] = __floats2bfloat162_rn(v.z - hz, v.w - hw);
}

__global__ __launch_bounds__(256) void k_split_w(const float* __restrict__ w_ih) {
    int idx = blockIdx.x * 256 + threadIdx.x;
    float4 v = *(const float4*)(w_ih + (size_t)idx * 4);
    float hx = __bfloat162float(__float2bfloat16(v.x));
    float hy = __bfloat162float(__float2bfloat16(v.y));
    float hz = __bfloat162float(__float2bfloat16(v.z));
    float hw = __bfloat162float(__float2bfloat16(v.w));
    ((__nv_bfloat162*)g_wh)[idx * 2]     = __floats2bfloat162_rn(hx, hy);
    ((__nv_bfloat162*)g_wh)[idx * 2 + 1] = __floats2bfloat162_rn(hz, hw);
    ((__nv_bfloat162*)g_wl)[idx * 2]     = __floats2bfloat162_rn(v.x - hx, v.y - hy);
    ((__nv_bfloat162*)g_wl)[idx * 2 + 1] = __floats2bfloat162_rn(v.z - hz, v.w - hw);
}

// ============ prep: w_hh -> tf32 hi/lo B-fragment layout
__global__ __launch_bounds__(256) void k_prep_w(const float* __restrict__ w_hh) {
    int bid = blockIdx.x;
    int c0 = bid * 8;
    for (int it = 0; it < WFB / 256; it++) {
        int idx = it * 256 + threadIdx.x;
        int word = idx & 3;
        int lane = (idx >> 2) & 31;
        int rest = idx >> 7;
        int j = rest % 3; rest /= 3;
        int q = rest % 12;
        int ks = rest / 12;
        int lrow = lane >> 2;                       // n within tile = gate col
        int gr = (j == 0) ? (c0 + lrow)
               : (j == 1) ? (Dn + c0 + lrow) : (2 * Dn + c0 + lrow);
        int k = ks * 96 + q * 8 + (lane & 3) + ((word & 1) * 4);
        float w = w_hh[(size_t)gr * Dn + k];
        float hi = __uint_as_float(__float_as_uint(w) & 0xffffe000u);
        float vv = (word < 2) ? hi : (w - hi);
        g_wfrag[(size_t)bid * WFB + idx] = vv;
    }
}

// ============ Kernel 1: xp via mma.sync bf16 3-term split (unchanged, passing)
__device__ __forceinline__ void mma_bf16(float* c, const unsigned* a, const unsigned* b) {
    asm volatile(
        "mma.sync.aligned.m16n8k16.row.col.f32.bf16.bf16.f32 "
        "{%0,%1,%2,%3}, {%4,%5,%6,%7}, {%8,%9}, {%0,%1,%2,%3};"
        : "+f"(c[0]), "+f"(c[1]), "+f"(c[2]), "+f"(c[3])
        : "r"(a[0]), "r"(a[1]), "r"(a[2]), "r"(a[3]), "r"(b[0]), "r"(b[1]));
}

__global__ __launch_bounds__(256, 1) void k_xp_mma(const float* __restrict__ b_ih) {
    __shared__ unsigned Ah[2][8][32][4];
    __shared__ unsigned Al[2][8][32][4];
    __shared__ unsigned Bh[2][16][32][2];
    __shared__ unsigned Bl[2][16][32][2];

    const int tid = threadIdx.x;
    const int bm = blockIdx.y * 128;
    const int bn = blockIdx.x * 128;
    const int warp = tid >> 5;
    const int lane = tid & 31;
    const int wm = warp >> 2;
    const int wn = warp & 3;
    const int gid = lane >> 2;
    const int tig = lane & 3;

    const int lrow = tid >> 1;
    const int hs = tid & 1;
    const int lmt = lrow >> 4;
    const int lnt = lrow >> 3;
    const int lml = (lrow & 7) * 4;
    const int lreg = (lrow >> 3) & 1;

    const uint4* xh = (const uint4*)(g_xh + (size_t)(bm + lrow) * Dn + hs * 8);
    const uint4* xl = (const uint4*)(g_xl + (size_t)(bm + lrow) * Dn + hs * 8);
    const uint4* wh = (const uint4*)(g_wh + (size_t)(bn + lrow) * Dn + hs * 8);
    const uint4* wl = (const uint4*)(g_wl + (size_t)(bn + lrow) * Dn + hs * 8);

    float acc[4][4][4];
#pragma unroll
    for (int i = 0; i < 4; i++)
#pragma unroll
        for (int j = 0; j < 4; j++)
#pragma unroll
            for (int r = 0; r < 4; r++) acc[i][j][r] = 0.f;

    {
        uint4 va = xh[0], vb = xl[0], vc = wh[0], vd = wl[0];
        const unsigned* aw = (const unsigned*)&va;
        const unsigned* bw = (const unsigned*)&vb;
        const unsigned* cw = (const unsigned*)&vc;
        const unsigned* dw = (const unsigned*)&vd;
#pragma unroll
        for (int j = 0; j < 4; j++) {
            Ah[0][lmt][lml + j][lreg + 2 * hs] = aw[j];
            Al[0][lmt][lml + j][lreg + 2 * hs] = bw[j];
            Bh[0][lnt][lml + j][hs] = cw[j];
            Bl[0][lnt][lml + j][hs] = dw[j];
        }
    }

    for (int kt = 0; kt < 48; kt++) {
        const int cb = kt & 1;
        uint4 va, vb, vc, vd;
        if (kt + 1 < 48) {
            va = xh[(kt + 1) * 2]; vb = xl[(kt + 1) * 2];
            vc = wh[(kt + 1) * 2]; vd = wl[(kt + 1) * 2];
        }
        __syncthreads();

        unsigned ah[4][4], al[4][4], bh[4][2], bl[4][2];
#pragma unroll
        for (int i = 0; i < 4; i++) {
            *(uint4*)ah[i] = *(const uint4*)&Ah[cb][wm * 4 + i][lane][0];
            *(uint4*)al[i] = *(const uint4*)&Al[cb][wm * 4 + i][lane][0];
        }
#pragma unroll
        for (int j = 0; j < 4; j++) {
            *(uint2*)bh[j] = *(const uint2*)&Bh[cb][wn * 4 + j][lane][0];
            *(uint2*)bl[j] = *(const uint2*)&Bl[cb][wn * 4 + j][lane][0];
        }
#pragma unroll
        for (int i = 0; i < 4; i++)
#pragma unroll
            for (int j = 0; j < 4; j++) {
                mma_bf16(acc[i][j], ah[i], bh[j]);
                mma_bf16(acc[i][j], al[i], bh[j]);
                mma_bf16(acc[i][j], ah[i], bl[j]);
            }

        if (kt + 1 < 48) {
            const int nb = (kt + 1) & 1;
            const unsigned* aw = (const unsigned*)&va;
            const unsigned* bw = (const unsigned*)&vb;
            const unsigned* cw = (const unsigned*)&vc;
            const unsigned* dw = (const unsigned*)&vd;
#pragma unroll
            for (int j = 0; j < 4; j++) {
                Ah[nb][lmt][lml + j][lreg + 2 * hs] = aw[j];
                Al[nb][lmt][lml + j][lreg + 2 * hs] = bw[j];
                Bh[nb][lnt][lml + j][hs] = cw[j];
                Bl[nb][lnt][lml + j][hs] = dw[j];
            }
        }
    }

#pragma unroll
    for (int j = 0; j < 4; j++) {
        int ncol = bn + (wn * 4 + j) * 8 + 2 * tig;
        float2 bias = *(const float2*)&b_ih[ncol];
#pragma unroll
        for (int i = 0; i < 4; i++) {
            int m0 = bm + (wm * 4 + i) * 16 + gid;
            float2 v0 = {acc[i][j][0] + bias.x, acc[i][j][1] + bias.y};
            float2 v1 = {acc[i][j][2] + bias.x, acc[i][j][3] + bias.y};
            *(float2*)(g_xp + (size_t)m0 * D3 + ncol) = v0;
            *(float2*)(g_xp + (size_t)(m0 + 8) * D3 + ncol) = v1;
        }
    }
}

// ============ Kernel 2: persistent GRU with 3xTF32 mma
#define SM_WF WFB                       // 36864 floats
#define SM_PART (8 * 24 * 33)
#define SMEM_GRU ((SM_WF + SM_PART) * 4)

__device__ __forceinline__ void gbar(int phase) {
    __syncthreads();
    if (threadIdx.x == 0) {
        __threadfence();
        g_flag[blockIdx.x] = phase;
    }
    if ((int)threadIdx.x < NB) {
        while (g_flag[threadIdx.x] < phase) {}
    }
    __threadfence();
    __syncthreads();
}

__device__ __forceinline__ void mma_tf32(float* c, const float4 a, float b0, float b1) {
    asm volatile(
        "mma.sync.aligned.m16n8k8.row.col.f32.tf32.tf32.f32 "
        "{%0,%1,%2,%3}, {%4,%5,%6,%7}, {%8,%9}, {%0,%1,%2,%3};"
        : "+f"(c[0]), "+f"(c[1]), "+f"(c[2]), "+f"(c[3])
        : "r"(__float_as_uint(a.x)), "r"(__float_as_uint(a.y)),
          "r"(__float_as_uint(a.z)), "r"(__float_as_uint(a.w)),
          "r"(__float_as_uint(b0)), "r"(__float_as_uint(b1)));
}

__device__ __forceinline__ float4 tf_hi(float4 a) {
    float4 h;
    h.x = __uint_as_float(__float_as_uint(a.x) & 0xffffe000u);
    h.y = __uint_as_float(__float_as_uint(a.y) & 0xffffe000u);
    h.z = __uint_as_float(__float_as_uint(a.z) & 0xffffe000u);
    h.w = __uint_as_float(__float_as_uint(a.w) & 0xffffe000u);
    return h;
}
__device__ __forceinline__ float4 f4sub(float4 a, float4 b) {
    return make_float4(a.x - b.x, a.y - b.y, a.z - b.z, a.w - b.w);
}

__global__ __launch_bounds__(256, 1) void k_gru(const float* __restrict__ b_hh) {
    extern __shared__ float sm[];
    float* wf = sm;                 // [ks][q][j][lane][4]
    float* part = sm + SM_WF;       // [ks][24][33]

    const int tid = threadIdx.x;
    const int bid = blockIdx.x;
    const int c0 = bid * 8;

    // load this block's w fragments
    {
        const float4* src = (const float4*)(g_wfrag + (size_t)bid * WFB);
        float4* dst = (float4*)wf;
        for (int i = tid; i < WFB / 4; i += 256) dst[i] = src[i];
    }

    const int lane = tid & 31;
    const int ks = tid >> 5;

    // gate identity (all 256 threads: 8 cols x 32 batches)
    const int gc = tid >> 5;
    const int gb = tid & 31;
    const float br = b_hh[c0 + gc];
    const float bz = b_hh[Dn + c0 + gc];
    const float bnn = b_hh[2 * Dn + c0 + gc];
    // this thread's h element position in frag layout (ktile == bid)
    const int gw = ((gb >> 4) * 96 + bid) * 128 +
                   ((gb & 7) * 4 + (gc & 3)) * 4 + ((gc >> 2) * 2 + ((gb & 15) >> 3));
    float hold = 0.f;

    g_hfrag[gw] = 0.f;   // parity 0 init (each block zeroes exactly its slice)
    gbar(1);

    for (int t = 0; t < Tn; t++) {
        const int par = t & 1;

        size_t mrow = (size_t)(gb * Tn + t) * D3 + c0 + gc;
        float xr = g_xp[mrow];
        float xz = g_xp[mrow + Dn];
        float xn = g_xp[mrow + 2 * Dn];

        const float* hf = g_hfrag + (size_t)par * HFP;
        const int a0 = (0 * 96 + ks * 12) * 128 + lane * 4;
        const int a1 = (1 * 96 + ks * 12) * 128 + lane * 4;

        float acc[2][3][4];
#pragma unroll
        for (int mt = 0; mt < 2; mt++)
#pragma unroll
            for (int j = 0; j < 3; j++)
#pragma unroll
                for (int r = 0; r < 4; r++) acc[mt][j][r] = 0.f;

        float4 cur0 = __ldcv((const float4*)(hf + a0));
        float4 cur1 = __ldcv((const float4*)(hf + a1));
#pragma unroll
        for (int q = 0; q < 12; q++) {
            float4 nxt0, nxt1;
            if (q + 1 < 12) {
                nxt0 = __ldcv((const float4*)(hf + a0 + (q + 1) * 128));
                nxt1 = __ldcv((const float4*)(hf + a1 + (q + 1) * 128));
            }
            float4 h0 = tf_hi(cur0), l0 = f4sub(cur0, h0);
            float4 h1 = tf_hi(cur1), l1 = f4sub(cur1, h1);
#pragma unroll
            for (int j = 0; j < 3; j++) {
                float4 bf = *(const float4*)&wf[(((ks * 12 + q) * 3) + j) * 128 + lane * 4];
                // bf = {b0h, b1h, b0l, b1l}
                mma_tf32(acc[0][j], h0, bf.x, bf.y);
                mma_tf32(acc[0][j], l0, bf.x, bf.y);
                mma_tf32(acc[0][j], h0, bf.z, bf.w);
                mma_tf32(acc[1][j], h1, bf.x, bf.y);
                mma_tf32(acc[1][j], l1, bf.x, bf.y);
                mma_tf32(acc[1][j], h1, bf.z, bf.w);
            }
            cur0 = nxt0; cur1 = nxt1;
        }

        // scatter C frags to partials: row = j*8 + 2*(lane&3) + (r&1),
        // batch = 16*mt + (lane>>2) + 8*(r>>1)
#pragma unroll
        for (int mt = 0; mt < 2; mt++)
#pragma unroll
            for (int j = 0; j < 3; j++)
#pragma unroll
                for (int r = 0; r < 4; r++)
                    part[ks * 792 + (j * 8 + 2 * (lane & 3) + (r & 1)) * 33 +
                         (16 * mt + (lane >> 2) + 8 * (r >> 1))] = acc[mt][j][r];
        __syncthreads();

        // gate math (256 threads = 8 cols x 32 batches)
        {
            float hr = br, hz = bz, hn = bnn;
#pragma unroll
            for (int s2 = 0; s2 < 8; s2++) {
                const float* pp = part + s2 * 792;
                hr += pp[gc * 33 + gb];
                hz += pp[(8 + gc) * 33 + gb];
                hn += pp[(16 + gc) * 33 + gb];
            }
            float r = 1.f / (1.f + expf(-(xr + hr)));
            float z = 1.f / (1.f + expf(-(xz + hz)));
            float n = tanhf(xn + r * hn);
            float hnew = (1.f - z) * n + z * hold;
            hold = hnew;
            g_hfrag[(size_t)(par ^ 1) * HFP + gw] = hnew;
            g_states[(size_t)(gb * Tn + t) * Dn + c0 + gc] = hnew;
        }

        gbar(t + 2);
    }

    if (tid == 0) {
        int old = atomicAdd(&g_done, 1);
        if (old == NB - 1) {
            for (int i = 0; i < NB; i++) g_flag[i] = 0;
            __threadfence();
            g_done = 0;
        }
    }
}

// ============ Kernel 3: probs
__global__ __launch_bounds__(256) void k_probs(const float* __restrict__ w_act,
                                               const float* __restrict__ b_act,
                                               float* __restrict__ out_probs) {
    int warp = threadIdx.x >> 5, lane = threadIdx.x & 31;
    int m = blockIdx.x * 8 + warp;
    const float4* row = (const float4*)(g_states + (size_t)m * Dn);
    const float4* wv = (const float4*)w_act;
    float acc = 0.f;
    for (int i = lane; i < 192; i += 32) {
        float4 v = row[i], w = wv[i];
        acc += v.x * w.x + v.y * w.y + v.z * w.z + v.w * w.w;
    }
#pragma unroll
    for (int off = 16; off; off >>= 1) acc += __shfl_down_sync(0xffffffffu, acc, off);
    if (lane == 0) {
        float p = 1.f / (1.f + expf(-(acc + b_act[0])));
        g_probs[m] = p;
        out_probs[m] = p;
    }
}

// ============ Kernel 4: ACT halting scan
__global__ void k_halt() {
    extern __shared__ float ps[];
    int tid = threadIdx.x;
    for (int i = tid; i < Bn * Tn; i += 384) {
        int b = i / Tn, t = i - b * Tn;
        ps[b * (Tn + 1) + t] = g_probs[i];
    }
    __syncthreads();
    if (tid < Bn) {
        int b = tid;
        const float* pb = ps + b * (Tn + 1);
        float acc = 0.f;
        int ns = 0;
        for (int t = 0; t < Tn; t++) {
            float p = pb[t];
            float a = acc + p;
            if (a > THRESH) {
                g_weights[b * Tn + t] = p - (a - 1.f);
                g_segend[b * Tn + ns] = t;
                ns++;
                acc = 0.f;
            } else {
                g_weights[b * Tn + t] = p;
                acc = a;
            }
        }
        g_nsegs[b] = ns;
    }
}

// ============ Kernel 5: segment sums -> output embs
__global__ __launch_bounds__(128) void k_out(float* __restrict__ out) {
    int bs = blockIdx.x;
    int b = bs / Tn, s = bs - b * Tn;
    float* o = out + (size_t)bs * Dn;
    int tid = threadIdx.x;
    if (s >= g_nsegs[b]) {
        for (int d = tid; d < Dn; d += 128) o[d] = 0.f;
        return;
    }
    int t1 = g_segend[b * Tn + s];
    int t0 = (s == 0) ? 0 : g_segend[b * Tn + s - 1] + 1;
    for (int d = tid; d < Dn; d += 128) {
        float sum = 0.f;
        for (int t = t0; t <= t1; t++)
            sum += g_states[(size_t)(b * Tn + t) * Dn + d] * g_weights[b * Tn + t];
        o[d] = sum;
    }
}

extern "C" void kernel_launch(void* const* d_in, const int* in_sizes, int n_in,
                              void* d_out, int out_size) {
    const int* sent    = (const int*)d_in[0];
    const float* emb   = (const float*)d_in[1];
    const float* w_ih  = (const float*)d_in[2];
    const float* w_hh  = (const float*)d_in[3];
    const float* b_ih  = (const float*)d_in[4];
    const float* b_hh  = (const float*)d_in[5];
    const float* w_act = (const float*)d_in[6];
    const float* b_act = (const float*)d_in[7];
    float* out = (float*)d_out;

    cudaFuncSetAttribute(k_gru, cudaFuncAttributeMaxDynamicSharedMemorySize, SMEM_GRU);
    cudaFuncSetAttribute(k_halt, cudaFuncAttributeMaxDynamicSharedMemorySize,
                         Bn * (Tn + 1) * 4);

    k_split_x<<<(Bn * Tn * 192) / 256, 256>>>(sent, emb);
    k_split_w<<<(D3 * 192) / 256, 256>>>(w_ih);
    k_prep_w<<<NB, 256>>>(w_hh);
    k_xp_mma<<<dim3(D3 / 128, (Bn * Tn) / 128), 256>>>(b_ih);
    k_gru<<<NB, 256, SMEM_GRU>>>(b_hh);
    k_probs<<<(Bn * Tn) / 8, 256>>>(w_act, b_act, out + (size_t)Bn * Tn * Dn);
    k_halt<<<1, 384, Bn * (Tn + 1) * 4>>>();
    k_out<<<Bn * Tn, 128>>>(out);
}

// round 10
// speedup vs baseline: 1.3453x; 1.0612x over previous
#include <cuda_runtime.h>
#include <cuda_bf16.h>
#include <math.h>

#define Bn 32
#define Tn 384
#define Dn 768
#define D3 2304
#define NB 96
#define GRP_NB 48
#define THRESH 0.95f

__device__ float g_xp[(size_t)Bn * Tn * D3];
__device__ float g_states[(size_t)Bn * Tn * Dn];
__device__ float g_probs[Bn * Tn];
__device__ float g_weights[Bn * Tn];
__device__ int   g_segend[Bn * Tn];
__device__ int   g_nsegs[Bn];
__device__ volatile int g_flag[NB];
__device__ int   g_done;

// h exchange in m16n8k8 A-frag layout, per group+parity: [grp][par][96 ktile][128]
__device__ float g_hfrag[2][2][96 * 128];
// w_hh fp32 fragment-permuted per column-slice: [cidx 48][ks 8][q 12][nt 6][lane 32][2]
#define WFG (8 * 12 * 6 * 32 * 2)
__device__ float g_wfrag[(size_t)GRP_NB * WFG];

// bf16 hi/lo split planes for xp GEMM
__device__ __nv_bfloat16 g_xh[(size_t)Bn * Tn * Dn];
__device__ __nv_bfloat16 g_xl[(size_t)Bn * Tn * Dn];
__device__ __nv_bfloat16 g_wh[(size_t)D3 * Dn];
__device__ __nv_bfloat16 g_wl[(size_t)D3 * Dn];

// ============ split kernels for xp
__global__ __launch_bounds__(256) void k_split_x(const int* __restrict__ sent,
                                                 const float* __restrict__ emb) {
    int idx = blockIdx.x * 256 + threadIdx.x;
    int m = idx / 192, c4 = idx - (idx / 192) * 192;
    int tok = sent[m];
    float4 v = *(const float4*)(emb + (size_t)tok * Dn + c4 * 4);
    float hx = __bfloat162float(__float2bfloat16(v.x));
    float hy = __bfloat162float(__float2bfloat16(v.y));
    float hz = __bfloat162float(__float2bfloat16(v.z));
    float hw = __bfloat162float(__float2bfloat16(v.w));
    ((__nv_bfloat162*)g_xh)[m * 384 + c4 * 2]     = __floats2bfloat162_rn(hx, hy);
    ((__nv_bfloat162*)g_xh)[m * 384 + c4 * 2 + 1] = __floats2bfloat162_rn(hz, hw);
    ((__nv_bfloat162*)g_xl)[m * 384 + c4 * 2]     = __floats2bfloat162_rn(v.x - hx, v.y - hy);
    ((__nv_bfloat162*)g_xl)[m * 384 + c4 * 2 + 1] = __floats2bfloat162_rn(v.z - hz, v.w - hw);
}

__global__ __launch_bounds__(256) void k_split_w(const float* __restrict__ w_ih) {
    int idx = blockIdx.x * 256 + threadIdx.x;
    float4 v = *(const float4*)(w_ih + (size_t)idx * 4);
    float hx = __bfloat162float(__float2bfloat16(v.x));
    float hy = __bfloat162float(__float2bfloat16(v.y));
    float hz = __bfloat162float(__float2bfloat16(v.z));
    float hw = __bfloat162float(__float2bfloat16(v.w));
    ((__nv_bfloat162*)g_wh)[idx * 2]     = __floats2bfloat162_rn(hx, hy);
    ((__nv_bfloat162*)g_wh)[idx * 2 + 1] = __floats2bfloat162_rn(hz, hw);
    ((__nv_bfloat162*)g_wl)[idx * 2]     = __floats2bfloat162_rn(v.x - hx, v.y - hy);
    ((__nv_bfloat162*)g_wl)[idx * 2 + 1] = __floats2bfloat162_rn(v.z - hz, v.w - hw);
}

// ============ prep: w_hh -> fp32 B-fragment layout (per 16-col slice)
// local row n = gate j*16 + col; frag: [ks][q][nt][lane][2]
__global__ __launch_bounds__(256) void k_prep_w(const float* __restrict__ w_hh) {
    int cidx = blockIdx.x;
    int c0 = cidx * 16;
    for (int it = 0; it < WFG / 256; it++) {
        int idx = it * 256 + threadIdx.x;
        int word = idx & 1;
        int lane = (idx >> 1) & 31;
        int f = idx >> 6;
        int nt = f % 6;
        int q = (f / 6) % 12;
        int ks = f / 72;
        int n = nt * 8 + (lane >> 2);
        int j = n >> 4, col = n & 15;
        int gr = j * Dn + c0 + col;
        int k = ks * 96 + q * 8 + (lane & 3) + 4 * word;
        g_wfrag[(size_t)cidx * WFG + idx] = w_hh[(size_t)gr * Dn + k];
    }
}

// ============ Kernel 1: xp via mma.sync bf16 3-term split (unchanged)
__device__ __forceinline__ void mma_bf16(float* c, const unsigned* a, const unsigned* b) {
    asm volatile(
        "mma.sync.aligned.m16n8k16.row.col.f32.bf16.bf16.f32 "
        "{%0,%1,%2,%3}, {%4,%5,%6,%7}, {%8,%9}, {%0,%1,%2,%3};"
        : "+f"(c[0]), "+f"(c[1]), "+f"(c[2]), "+f"(c[3])
        : "r"(a[0]), "r"(a[1]), "r"(a[2]), "r"(a[3]), "r"(b[0]), "r"(b[1]));
}

__global__ __launch_bounds__(256, 1) void k_xp_mma(const float* __restrict__ b_ih) {
    __shared__ unsigned Ah[2][8][32][4];
    __shared__ unsigned Al[2][8][32][4];
    __shared__ unsigned Bh[2][16][32][2];
    __shared__ unsigned Bl[2][16][32][2];

    const int tid = threadIdx.x;
    const int bm = blockIdx.y * 128;
    const int bn = blockIdx.x * 128;
    const int warp = tid >> 5;
    const int lane = tid & 31;
    const int wm = warp >> 2;
    const int wn = warp & 3;
    const int gid = lane >> 2;
    const int tig = lane & 3;

    const int lrow = tid >> 1;
    const int hs = tid & 1;
    const int lmt = lrow >> 4;
    const int lnt = lrow >> 3;
    const int lml = (lrow & 7) * 4;
    const int lreg = (lrow >> 3) & 1;

    const uint4* xh = (const uint4*)(g_xh + (size_t)(bm + lrow) * Dn + hs * 8);
    const uint4* xl = (const uint4*)(g_xl + (size_t)(bm + lrow) * Dn + hs * 8);
    const uint4* wh = (const uint4*)(g_wh + (size_t)(bn + lrow) * Dn + hs * 8);
    const uint4* wl = (const uint4*)(g_wl + (size_t)(bn + lrow) * Dn + hs * 8);

    float acc[4][4][4];
#pragma unroll
    for (int i = 0; i < 4; i++)
#pragma unroll
        for (int j = 0; j < 4; j++)
#pragma unroll
            for (int r = 0; r < 4; r++) acc[i][j][r] = 0.f;

    {
        uint4 va = xh[0], vb = xl[0], vc = wh[0], vd = wl[0];
        const unsigned* aw = (const unsigned*)&va;
        const unsigned* bw = (const unsigned*)&vb;
        const unsigned* cw = (const unsigned*)&vc;
        const unsigned* dw = (const unsigned*)&vd;
#pragma unroll
        for (int j = 0; j < 4; j++) {
            Ah[0][lmt][lml + j][lreg + 2 * hs] = aw[j];
            Al[0][lmt][lml + j][lreg + 2 * hs] = bw[j];
            Bh[0][lnt][lml + j][hs] = cw[j];
            Bl[0][lnt][lml + j][hs] = dw[j];
        }
    }

    for (int kt = 0; kt < 48; kt++) {
        const int cb = kt & 1;
        uint4 va, vb, vc, vd;
        if (kt + 1 < 48) {
            va = xh[(kt + 1) * 2]; vb = xl[(kt + 1) * 2];
            vc = wh[(kt + 1) * 2]; vd = wl[(kt + 1) * 2];
        }
        __syncthreads();

        unsigned ah[4][4], al[4][4], bh[4][2], bl[4][2];
#pragma unroll
        for (int i = 0; i < 4; i++) {
            *(uint4*)ah[i] = *(const uint4*)&Ah[cb][wm * 4 + i][lane][0];
            *(uint4*)al[i] = *(const uint4*)&Al[cb][wm * 4 + i][lane][0];
        }
#pragma unroll
        for (int j = 0; j < 4; j++) {
            *(uint2*)bh[j] = *(const uint2*)&Bh[cb][wn * 4 + j][lane][0];
            *(uint2*)bl[j] = *(const uint2*)&Bl[cb][wn * 4 + j][lane][0];
        }
#pragma unroll
        for (int i = 0; i < 4; i++)
#pragma unroll
            for (int j = 0; j < 4; j++) {
                mma_bf16(acc[i][j], ah[i], bh[j]);
                mma_bf16(acc[i][j], al[i], bh[j]);
                mma_bf16(acc[i][j], ah[i], bl[j]);
            }

        if (kt + 1 < 48) {
            const int nb = (kt + 1) & 1;
            const unsigned* aw = (const unsigned*)&va;
            const unsigned* bw = (const unsigned*)&vb;
            const unsigned* cw = (const unsigned*)&vc;
            const unsigned* dw = (const unsigned*)&vd;
#pragma unroll
            for (int j = 0; j < 4; j++) {
                Ah[nb][lmt][lml + j][lreg + 2 * hs] = aw[j];
                Al[nb][lmt][lml + j][lreg + 2 * hs] = bw[j];
                Bh[nb][lnt][lml + j][hs] = cw[j];
                Bl[nb][lnt][lml + j][hs] = dw[j];
            }
        }
    }

#pragma unroll
    for (int j = 0; j < 4; j++) {
        int ncol = bn + (wn * 4 + j) * 8 + 2 * tig;
        float2 bias = *(const float2*)&b_ih[ncol];
#pragma unroll
        for (int i = 0; i < 4; i++) {
            int m0 = bm + (wm * 4 + i) * 16 + gid;
            float2 v0 = {acc[i][j][0] + bias.x, acc[i][j][1] + bias.y};
            float2 v1 = {acc[i][j][2] + bias.x, acc[i][j][3] + bias.y};
            *(float2*)(g_xp + (size_t)m0 * D3 + ncol) = v0;
            *(float2*)(g_xp + (size_t)(m0 + 8) * D3 + ncol) = v1;
        }
    }
}

// ============ Kernel 2: GRU, 2 independent groups of 48 blocks.
// Group owns 16 batches; block owns 16 cols; 3xTF32 mma, M=16 A-tile.
#define SM_PARTG (8 * 48 * 17)
#define SMEM_GRU ((WFG + SM_PARTG) * 4)

__device__ __forceinline__ void mma_tf32(float* c, const float4 a, float b0, float b1) {
    asm volatile(
        "mma.sync.aligned.m16n8k8.row.col.f32.tf32.tf32.f32 "
        "{%0,%1,%2,%3}, {%4,%5,%6,%7}, {%8,%9}, {%0,%1,%2,%3};"
        : "+f"(c[0]), "+f"(c[1]), "+f"(c[2]), "+f"(c[3])
        : "r"(__float_as_uint(a.x)), "r"(__float_as_uint(a.y)),
          "r"(__float_as_uint(a.z)), "r"(__float_as_uint(a.w)),
          "r"(__float_as_uint(b0)), "r"(__float_as_uint(b1)));
}
__device__ __forceinline__ float tf_hi1(float a) {
    return __uint_as_float(__float_as_uint(a) & 0xffffe000u);
}
__device__ __forceinline__ float4 tf_hi(float4 a) {
    return make_float4(tf_hi1(a.x), tf_hi1(a.y), tf_hi1(a.z), tf_hi1(a.w));
}
__device__ __forceinline__ float4 f4sub(float4 a, float4 b) {
    return make_float4(a.x - b.x, a.y - b.y, a.z - b.z, a.w - b.w);
}

__global__ __launch_bounds__(256, 1) void k_gru(const float* __restrict__ b_hh) {
    extern __shared__ float sm[];
    float* wf = sm;                  // [ks][q][nt][lane][2]
    float* part = sm + WFG;          // [ks][48][17]

    const int tid = threadIdx.x;
    const int bid = blockIdx.x;
    const int grp = bid / GRP_NB;
    const int cidx = bid - grp * GRP_NB;
    const int c0 = cidx * 16;
    const int b0 = grp * 16;

    // load this slice's w fragments
    {
        const float4* src = (const float4*)(g_wfrag + (size_t)cidx * WFG);
        float4* dst = (float4*)wf;
        for (int i = tid; i < WFG / 4; i += 256) dst[i] = src[i];
    }

    const int lane = tid & 31;
    const int ks = tid >> 5;

    // gate identity: 16 cols x 16 batches
    const int gc = tid >> 4;
    const int gb = tid & 15;
    const float br = b_hh[c0 + gc];
    const float bz = b_hh[Dn + c0 + gc];
    const float bnn = b_hh[2 * Dn + c0 + gc];
    // frag position of h[gb][c0+gc]
    const int c = c0 + gc;
    const int ktile = c >> 3, kin = c & 7;
    const int gw = ktile * 128 + ((gb & 7) * 4 + (kin & 3)) * 4 +
                   ((gb >> 3) + 2 * (kin >> 2));
    float hold = 0.f;

    g_hfrag[grp][0][gw] = 0.f;
    // group barrier init
    __syncthreads();
    if (tid == 0) { __threadfence(); g_flag[bid] = 1; }
    if (tid < GRP_NB) { while (g_flag[grp * GRP_NB + tid] < 1) {} }
    __threadfence();
    __syncthreads();

    for (int t = 0; t < Tn; t++) {
        const int par = t & 1;

        size_t mrow = (size_t)((b0 + gb) * Tn + t) * D3 + c0 + gc;
        float xr = g_xp[mrow];
        float xz = g_xp[mrow + Dn];
        float xn = g_xp[mrow + 2 * Dn];

        const float* hf = g_hfrag[grp][par];
        const int abase = (ks * 12) * 128 + lane * 4;

        float acc[6][4];
#pragma unroll
        for (int nt = 0; nt < 6; nt++)
#pragma unroll
            for (int r = 0; r < 4; r++) acc[nt][r] = 0.f;

        float4 cur = __ldcv((const float4*)(hf + abase));
#pragma unroll
        for (int q = 0; q < 12; q++) {
            float4 nxt;
            if (q + 1 < 12) nxt = __ldcv((const float4*)(hf + abase + (q + 1) * 128));
            float4 ahi = tf_hi(cur);
            float4 alo = f4sub(cur, ahi);
#pragma unroll
            for (int nt = 0; nt < 6; nt++) {
                float2 wv = *(const float2*)&wf[(((ks * 12 + q) * 6) + nt) * 64 + lane * 2];
                float bh0 = tf_hi1(wv.x), bh1 = tf_hi1(wv.y);
                float bl0 = wv.x - bh0, bl1 = wv.y - bh1;
                mma_tf32(acc[nt], ahi, bh0, bh1);
                mma_tf32(acc[nt], alo, bh0, bh1);
                mma_tf32(acc[nt], ahi, bl0, bl1);
            }
            cur = nxt;
        }

        // scatter C frags: n = nt*8 + (lane&3)*2 + (r&1), batch = (lane>>2) + 8*(r>>1)
#pragma unroll
        for (int nt = 0; nt < 6; nt++)
#pragma unroll
            for (int r = 0; r < 4; r++)
                part[ks * (48 * 17) + (nt * 8 + (lane & 3) * 2 + (r & 1)) * 17 +
                     (lane >> 2) + 8 * (r >> 1)] = acc[nt][r];
        __syncthreads();

        // gate math: 256 threads = 16 cols x 16 batches
        {
            float hr = br, hz = bz, hn = bnn;
#pragma unroll
            for (int s2 = 0; s2 < 8; s2++) {
                const float* pp = part + s2 * (48 * 17);
                hr += pp[gc * 17 + gb];
                hz += pp[(16 + gc) * 17 + gb];
                hn += pp[(32 + gc) * 17 + gb];
            }
            float r = 1.f / (1.f + expf(-(xr + hr)));
            float z = 1.f / (1.f + expf(-(xz + hz)));
            float n = tanhf(xn + r * hn);
            float hnew = (1.f - z) * n + z * hold;
            hold = hnew;
            g_hfrag[grp][par ^ 1][gw] = hnew;
            g_states[(size_t)((b0 + gb) * Tn + t) * Dn + c0 + gc] = hnew;
        }

        // group barrier
        __syncthreads();
        if (tid == 0) { __threadfence(); g_flag[bid] = t + 2; }
        if (tid < GRP_NB) { while (g_flag[grp * GRP_NB + tid] < t + 2) {} }
        __threadfence();
        __syncthreads();
    }

    // departure-counted reset (covers both groups)
    if (tid == 0) {
        int old = atomicAdd(&g_done, 1);
        if (old == NB - 1) {
            for (int i = 0; i < NB; i++) g_flag[i] = 0;
            __threadfence();
            g_done = 0;
        }
    }
}

// ============ Kernel 3: probs
__global__ __launch_bounds__(256) void k_probs(const float* __restrict__ w_act,
                                               const float* __restrict__ b_act,
                                               float* __restrict__ out_probs) {
    int warp = threadIdx.x >> 5, lane = threadIdx.x & 31;
    int m = blockIdx.x * 8 + warp;
    const float4* row = (const float4*)(g_states + (size_t)m * Dn);
    const float4* wv = (const float4*)w_act;
    float acc = 0.f;
    for (int i = lane; i < 192; i += 32) {
        float4 v = row[i], w = wv[i];
        acc += v.x * w.x + v.y * w.y + v.z * w.z + v.w * w.w;
    }
#pragma unroll
    for (int off = 16; off; off >>= 1) acc += __shfl_down_sync(0xffffffffu, acc, off);
    if (lane == 0) {
        float p = 1.f / (1.f + expf(-(acc + b_act[0])));
        g_probs[m] = p;
        out_probs[m] = p;
    }
}

// ============ Kernel 4: ACT halting scan
__global__ void k_halt() {
    extern __shared__ float ps[];
    int tid = threadIdx.x;
    for (int i = tid; i < Bn * Tn; i += 384) {
        int b = i / Tn, t = i - b * Tn;
        ps[b * (Tn + 1) + t] = g_probs[i];
    }
    __syncthreads();
    if (tid < Bn) {
        int b = tid;
        const float* pb = ps + b * (Tn + 1);
        float acc = 0.f;
        int ns = 0;
        for (int t = 0; t < Tn; t++) {
            float p = pb[t];
            float a = acc + p;
            if (a > THRESH) {
                g_weights[b * Tn + t] = p - (a - 1.f);
                g_segend[b * Tn + ns] = t;
                ns++;
                acc = 0.f;
            } else {
                g_weights[b * Tn + t] = p;
                acc = a;
            }
        }
        g_nsegs[b] = ns;
    }
}

// ============ Kernel 5: segment sums -> output embs
__global__ __launch_bounds__(128) void k_out(float* __restrict__ out) {
    int bs = blockIdx.x;
    int b = bs / Tn, s = bs - b * Tn;
    float* o = out + (size_t)bs * Dn;
    int tid = threadIdx.x;
    if (s >= g_nsegs[b]) {
        for (int d = tid; d < Dn; d += 128) o[d] = 0.f;
        return;
    }
    int t1 = g_segend[b * Tn + s];
    int t0 = (s == 0) ? 0 : g_segend[b * Tn + s - 1] + 1;
    for (int d = tid; d < Dn; d += 128) {
        float sum = 0.f;
        for (int t = t0; t <= t1; t++)
            sum += g_states[(size_t)(b * Tn + t) * Dn + d] * g_weights[b * Tn + t];
        o[d] = sum;
    }
}

extern "C" void kernel_launch(void* const* d_in, const int* in_sizes, int n_in,
                              void* d_out, int out_size) {
    const int* sent    = (const int*)d_in[0];
    const float* emb   = (const float*)d_in[1];
    const float* w_ih  = (const float*)d_in[2];
    const float* w_hh  = (const float*)d_in[3];
    const float* b_ih  = (const float*)d_in[4];
    const float* b_hh  = (const float*)d_in[5];
    const float* w_act = (const float*)d_in[6];
    const float* b_act = (const float*)d_in[7];
    float* out = (float*)d_out;

    cudaFuncSetAttribute(k_gru, cudaFuncAttributeMaxDynamicSharedMemorySize, SMEM_GRU);
    cudaFuncSetAttribute(k_halt, cudaFuncAttributeMaxDynamicSharedMemorySize,
                         Bn * (Tn + 1) * 4);

    k_split_x<<<(Bn * Tn * 192) / 256, 256>>>(sent, emb);
    k_split_w<<<(D3 * 192) / 256, 256>>>(w_ih);
    k_prep_w<<<GRP_NB, 256>>>(w_hh);
    k_xp_mma<<<dim3(D3 / 128, (Bn * Tn) / 128), 256>>>(b_ih);
    k_gru<<<NB, 256, SMEM_GRU>>>(b_hh);
    k_probs<<<(Bn * Tn) / 8, 256>>>(w_act, b_act, out + (size_t)Bn * Tn * Dn);
    k_halt<<<1, 384, Bn * (Tn + 1) * 4>>>();
    k_out<<<Bn * Tn, 128>>>(out);
}

// round 11
// speedup vs baseline: 1.4216x; 1.0567x over previous
#include <cuda_runtime.h>
#include <cuda_bf16.h>
#include <math.h>

#define Bn 32
#define Tn 384
#define Dn 768
#define D3 2304
#define NB 96
#define GRP_NB 48
#define THRESH 0.95f

__device__ float g_xp[(size_t)Bn * Tn * D3];
__device__ float g_states[(size_t)Bn * Tn * Dn];
__device__ float g_probs[Bn * Tn];
__device__ float g_weights[Bn * Tn];
__device__ int   g_segend[Bn * Tn];
__device__ int   g_nsegs[Bn];
__device__ volatile int g_flag[NB];
__device__ int   g_done;

// h exchange in m16n8k8 A-frag layout, per group+parity: [grp][par][96 ktile][128]
__device__ float g_hfrag[2][2][96 * 128];
// w_hh fp32 fragment-permuted per column-slice: [cidx 48][ks 8][q 12][nt 6][lane 32][2]
#define WFG (8 * 12 * 6 * 32 * 2)
__device__ float g_wfrag[(size_t)GRP_NB * WFG];

// bf16 hi/lo split planes for xp GEMM
__device__ __nv_bfloat16 g_xh[(size_t)Bn * Tn * Dn];
__device__ __nv_bfloat16 g_xl[(size_t)Bn * Tn * Dn];
__device__ __nv_bfloat16 g_wh[(size_t)D3 * Dn];
__device__ __nv_bfloat16 g_wl[(size_t)D3 * Dn];

// ============ split kernels for xp
__global__ __launch_bounds__(256) void k_split_x(const int* __restrict__ sent,
                                                 const float* __restrict__ emb) {
    int idx = blockIdx.x * 256 + threadIdx.x;
    int m = idx / 192, c4 = idx - (idx / 192) * 192;
    int tok = sent[m];
    float4 v = *(const float4*)(emb + (size_t)tok * Dn + c4 * 4);
    float hx = __bfloat162float(__float2bfloat16(v.x));
    float hy = __bfloat162float(__float2bfloat16(v.y));
    float hz = __bfloat162float(__float2bfloat16(v.z));
    float hw = __bfloat162float(__float2bfloat16(v.w));
    ((__nv_bfloat162*)g_xh)[m * 384 + c4 * 2]     = __floats2bfloat162_rn(hx, hy);
    ((__nv_bfloat162*)g_xh)[m * 384 + c4 * 2 + 1] = __floats2bfloat162_rn(hz, hw);
    ((__nv_bfloat162*)g_xl)[m * 384 + c4 * 2]     = __floats2bfloat162_rn(v.x - hx, v.y - hy);
    ((__nv_bfloat162*)g_xl)[m * 384 + c4 * 2 + 1] = __floats2bfloat162_rn(v.z - hz, v.w - hw);
}

__global__ __launch_bounds__(256) void k_split_w(const float* __restrict__ w_ih) {
    int idx = blockIdx.x * 256 + threadIdx.x;
    float4 v = *(const float4*)(w_ih + (size_t)idx * 4);
    float hx = __bfloat162float(__float2bfloat16(v.x));
    float hy = __bfloat162float(__float2bfloat16(v.y));
    float hz = __bfloat162float(__float2bfloat16(v.z));
    float hw = __bfloat162float(__float2bfloat16(v.w));
    ((__nv_bfloat162*)g_wh)[idx * 2]     = __floats2bfloat162_rn(hx, hy);
    ((__nv_bfloat162*)g_wh)[idx * 2 + 1] = __floats2bfloat162_rn(hz, hw);
    ((__nv_bfloat162*)g_wl)[idx * 2]     = __floats2bfloat162_rn(v.x - hx, v.y - hy);
    ((__nv_bfloat162*)g_wl)[idx * 2 + 1] = __floats2bfloat162_rn(v.z - hz, v.w - hw);
}

// ============ prep: w_hh -> fp32 B-fragment layout (per 16-col slice)
__global__ __launch_bounds__(256) void k_prep_w(const float* __restrict__ w_hh) {
    int cidx = blockIdx.x;
    int c0 = cidx * 16;
    for (int it = 0; it < WFG / 256; it++) {
        int idx = it * 256 + threadIdx.x;
        int word = idx & 1;
        int lane = (idx >> 1) & 31;
        int f = idx >> 6;
        int nt = f % 6;
        int q = (f / 6) % 12;
        int ks = f / 72;
        int n = nt * 8 + (lane >> 2);
        int j = n >> 4, col = n & 15;
        int gr = j * Dn + c0 + col;
        int k = ks * 96 + q * 8 + (lane & 3) + 4 * word;
        g_wfrag[(size_t)cidx * WFG + idx] = w_hh[(size_t)gr * Dn + k];
    }
}

// ============ Kernel 1: xp via mma.sync bf16 3-term split (unchanged)
__device__ __forceinline__ void mma_bf16(float* c, const unsigned* a, const unsigned* b) {
    asm volatile(
        "mma.sync.aligned.m16n8k16.row.col.f32.bf16.bf16.f32 "
        "{%0,%1,%2,%3}, {%4,%5,%6,%7}, {%8,%9}, {%0,%1,%2,%3};"
        : "+f"(c[0]), "+f"(c[1]), "+f"(c[2]), "+f"(c[3])
        : "r"(a[0]), "r"(a[1]), "r"(a[2]), "r"(a[3]), "r"(b[0]), "r"(b[1]));
}

__global__ __launch_bounds__(256, 1) void k_xp_mma(const float* __restrict__ b_ih) {
    __shared__ unsigned Ah[2][8][32][4];
    __shared__ unsigned Al[2][8][32][4];
    __shared__ unsigned Bh[2][16][32][2];
    __shared__ unsigned Bl[2][16][32][2];

    const int tid = threadIdx.x;
    const int bm = blockIdx.y * 128;
    const int bn = blockIdx.x * 128;
    const int warp = tid >> 5;
    const int lane = tid & 31;
    const int wm = warp >> 2;
    const int wn = warp & 3;
    const int gid = lane >> 2;
    const int tig = lane & 3;

    const int lrow = tid >> 1;
    const int hs = tid & 1;
    const int lmt = lrow >> 4;
    const int lnt = lrow >> 3;
    const int lml = (lrow & 7) * 4;
    const int lreg = (lrow >> 3) & 1;

    const uint4* xh = (const uint4*)(g_xh + (size_t)(bm + lrow) * Dn + hs * 8);
    const uint4* xl = (const uint4*)(g_xl + (size_t)(bm + lrow) * Dn + hs * 8);
    const uint4* wh = (const uint4*)(g_wh + (size_t)(bn + lrow) * Dn + hs * 8);
    const uint4* wl = (const uint4*)(g_wl + (size_t)(bn + lrow) * Dn + hs * 8);

    float acc[4][4][4];
#pragma unroll
    for (int i = 0; i < 4; i++)
#pragma unroll
        for (int j = 0; j < 4; j++)
#pragma unroll
            for (int r = 0; r < 4; r++) acc[i][j][r] = 0.f;

    {
        uint4 va = xh[0], vb = xl[0], vc = wh[0], vd = wl[0];
        const unsigned* aw = (const unsigned*)&va;
        const unsigned* bw = (const unsigned*)&vb;
        const unsigned* cw = (const unsigned*)&vc;
        const unsigned* dw = (const unsigned*)&vd;
#pragma unroll
        for (int j = 0; j < 4; j++) {
            Ah[0][lmt][lml + j][lreg + 2 * hs] = aw[j];
            Al[0][lmt][lml + j][lreg + 2 * hs] = bw[j];
            Bh[0][lnt][lml + j][hs] = cw[j];
            Bl[0][lnt][lml + j][hs] = dw[j];
        }
    }

    for (int kt = 0; kt < 48; kt++) {
        const int cb = kt & 1;
        uint4 va, vb, vc, vd;
        if (kt + 1 < 48) {
            va = xh[(kt + 1) * 2]; vb = xl[(kt + 1) * 2];
            vc = wh[(kt + 1) * 2]; vd = wl[(kt + 1) * 2];
        }
        __syncthreads();

        unsigned ah[4][4], al[4][4], bh[4][2], bl[4][2];
#pragma unroll
        for (int i = 0; i < 4; i++) {
            *(uint4*)ah[i] = *(const uint4*)&Ah[cb][wm * 4 + i][lane][0];
            *(uint4*)al[i] = *(const uint4*)&Al[cb][wm * 4 + i][lane][0];
        }
#pragma unroll
        for (int j = 0; j < 4; j++) {
            *(uint2*)bh[j] = *(const uint2*)&Bh[cb][wn * 4 + j][lane][0];
            *(uint2*)bl[j] = *(const uint2*)&Bl[cb][wn * 4 + j][lane][0];
        }
#pragma unroll
        for (int i = 0; i < 4; i++)
#pragma unroll
            for (int j = 0; j < 4; j++) {
                mma_bf16(acc[i][j], ah[i], bh[j]);
                mma_bf16(acc[i][j], al[i], bh[j]);
                mma_bf16(acc[i][j], ah[i], bl[j]);
            }

        if (kt + 1 < 48) {
            const int nb = (kt + 1) & 1;
            const unsigned* aw = (const unsigned*)&va;
            const unsigned* bw = (const unsigned*)&vb;
            const unsigned* cw = (const unsigned*)&vc;
            const unsigned* dw = (const unsigned*)&vd;
#pragma unroll
            for (int j = 0; j < 4; j++) {
                Ah[nb][lmt][lml + j][lreg + 2 * hs] = aw[j];
                Al[nb][lmt][lml + j][lreg + 2 * hs] = bw[j];
                Bh[nb][lnt][lml + j][hs] = cw[j];
                Bl[nb][lnt][lml + j][hs] = dw[j];
            }
        }
    }

#pragma unroll
    for (int j = 0; j < 4; j++) {
        int ncol = bn + (wn * 4 + j) * 8 + 2 * tig;
        float2 bias = *(const float2*)&b_ih[ncol];
#pragma unroll
        for (int i = 0; i < 4; i++) {
            int m0 = bm + (wm * 4 + i) * 16 + gid;
            float2 v0 = {acc[i][j][0] + bias.x, acc[i][j][1] + bias.y};
            float2 v1 = {acc[i][j][2] + bias.x, acc[i][j][3] + bias.y};
            *(float2*)(g_xp + (size_t)m0 * D3 + ncol) = v0;
            *(float2*)(g_xp + (size_t)(m0 + 8) * D3 + ncol) = v1;
        }
    }
}

// ============ Kernel 2: GRU, 2 groups of 48 blocks; h-frags batch-loaded (MLP 12)
#define SM_PARTG (8 * 48 * 17)
#define SMEM_GRU ((WFG + SM_PARTG) * 4)

__device__ __forceinline__ void mma_tf32(float* c, const float4 a, float b0, float b1) {
    asm volatile(
        "mma.sync.aligned.m16n8k8.row.col.f32.tf32.tf32.f32 "
        "{%0,%1,%2,%3}, {%4,%5,%6,%7}, {%8,%9}, {%0,%1,%2,%3};"
        : "+f"(c[0]), "+f"(c[1]), "+f"(c[2]), "+f"(c[3])
        : "r"(__float_as_uint(a.x)), "r"(__float_as_uint(a.y)),
          "r"(__float_as_uint(a.z)), "r"(__float_as_uint(a.w)),
          "r"(__float_as_uint(b0)), "r"(__float_as_uint(b1)));
}
__device__ __forceinline__ float tf_hi1(float a) {
    return __uint_as_float(__float_as_uint(a) & 0xffffe000u);
}
__device__ __forceinline__ float4 tf_hi(float4 a) {
    return make_float4(tf_hi1(a.x), tf_hi1(a.y), tf_hi1(a.z), tf_hi1(a.w));
}
__device__ __forceinline__ float4 f4sub(float4 a, float4 b) {
    return make_float4(a.x - b.x, a.y - b.y, a.z - b.z, a.w - b.w);
}

__global__ __launch_bounds__(256, 1) void k_gru(const float* __restrict__ b_hh) {
    extern __shared__ float sm[];
    float* wf = sm;                  // [ks][q][nt][lane][2]
    float* part = sm + WFG;          // [ks][48][17]

    const int tid = threadIdx.x;
    const int bid = blockIdx.x;
    const int grp = bid / GRP_NB;
    const int cidx = bid - grp * GRP_NB;
    const int c0 = cidx * 16;
    const int b0 = grp * 16;

    {
        const float4* src = (const float4*)(g_wfrag + (size_t)cidx * WFG);
        float4* dst = (float4*)wf;
        for (int i = tid; i < WFG / 4; i += 256) dst[i] = src[i];
    }

    const int lane = tid & 31;
    const int ks = tid >> 5;

    const int gc = tid >> 4;
    const int gb = tid & 15;
    const float br = b_hh[c0 + gc];
    const float bz = b_hh[Dn + c0 + gc];
    const float bnn = b_hh[2 * Dn + c0 + gc];
    const int c = c0 + gc;
    const int ktile = c >> 3, kin = c & 7;
    const int gw = ktile * 128 + ((gb & 7) * 4 + (kin & 3)) * 4 +
                   ((gb >> 3) + 2 * (kin >> 2));
    float hold = 0.f;

    g_hfrag[grp][0][gw] = 0.f;
    __syncthreads();
    if (tid == 0) { __threadfence(); g_flag[bid] = 1; }
    if (tid < GRP_NB) { while (g_flag[grp * GRP_NB + tid] < 1) {} }
    __threadfence();
    __syncthreads();

    for (int t = 0; t < Tn; t++) {
        const int par = t & 1;

        size_t mrow = (size_t)((b0 + gb) * Tn + t) * D3 + c0 + gc;
        float xr = g_xp[mrow];
        float xz = g_xp[mrow + Dn];
        float xn = g_xp[mrow + 2 * Dn];

        const float* hf = g_hfrag[grp][par];
        const int abase = (ks * 12) * 128 + lane * 4;

        // batch-issue ALL 12 h-frag loads (MLP=12): one exposed latency total
        float4 hreg[12];
#pragma unroll
        for (int q = 0; q < 12; q++)
            hreg[q] = __ldcv((const float4*)(hf + abase + q * 128));

        float acc[6][4];
#pragma unroll
        for (int nt = 0; nt < 6; nt++)
#pragma unroll
            for (int r = 0; r < 4; r++) acc[nt][r] = 0.f;

#pragma unroll
        for (int q = 0; q < 12; q++) {
            float4 ahi = tf_hi(hreg[q]);
            float4 alo = f4sub(hreg[q], ahi);
#pragma unroll
            for (int nt = 0; nt < 6; nt++) {
                float2 wv = *(const float2*)&wf[(((ks * 12 + q) * 6) + nt) * 64 + lane * 2];
                float bh0 = tf_hi1(wv.x), bh1 = tf_hi1(wv.y);
                float bl0 = wv.x - bh0, bl1 = wv.y - bh1;
                mma_tf32(acc[nt], ahi, bh0, bh1);
                mma_tf32(acc[nt], alo, bh0, bh1);
                mma_tf32(acc[nt], ahi, bl0, bl1);
            }
        }

#pragma unroll
        for (int nt = 0; nt < 6; nt++)
#pragma unroll
            for (int r = 0; r < 4; r++)
                part[ks * (48 * 17) + (nt * 8 + (lane & 3) * 2 + (r & 1)) * 17 +
                     (lane >> 2) + 8 * (r >> 1)] = acc[nt][r];
        __syncthreads();

        {
            float hr = br, hz = bz, hn = bnn;
#pragma unroll
            for (int s2 = 0; s2 < 8; s2++) {
                const float* pp = part + s2 * (48 * 17);
                hr += pp[gc * 17 + gb];
                hz += pp[(16 + gc) * 17 + gb];
                hn += pp[(32 + gc) * 17 + gb];
            }
            float r = 1.f / (1.f + expf(-(xr + hr)));
            float z = 1.f / (1.f + expf(-(xz + hz)));
            float n = tanhf(xn + r * hn);
            float hnew = (1.f - z) * n + z * hold;
            hold = hnew;
            g_hfrag[grp][par ^ 1][gw] = hnew;
            g_states[(size_t)((b0 + gb) * Tn + t) * Dn + c0 + gc] = hnew;
        }

        __syncthreads();
        if (tid == 0) { __threadfence(); g_flag[bid] = t + 2; }
        if (tid < GRP_NB) { while (g_flag[grp * GRP_NB + tid] < t + 2) {} }
        __threadfence();
        __syncthreads();
    }

    if (tid == 0) {
        int old = atomicAdd(&g_done, 1);
        if (old == NB - 1) {
            for (int i = 0; i < NB; i++) g_flag[i] = 0;
            __threadfence();
            g_done = 0;
        }
    }
}

// ============ Kernel 3: probs
__global__ __launch_bounds__(256) void k_probs(const float* __restrict__ w_act,
                                               const float* __restrict__ b_act,
                                               float* __restrict__ out_probs) {
    int warp = threadIdx.x >> 5, lane = threadIdx.x & 31;
    int m = blockIdx.x * 8 + warp;
    const float4* row = (const float4*)(g_states + (size_t)m * Dn);
    const float4* wv = (const float4*)w_act;
    float acc = 0.f;
    for (int i = lane; i < 192; i += 32) {
        float4 v = row[i], w = wv[i];
        acc += v.x * w.x + v.y * w.y + v.z * w.z + v.w * w.w;
    }
#pragma unroll
    for (int off = 16; off; off >>= 1) acc += __shfl_down_sync(0xffffffffu, acc, off);
    if (lane == 0) {
        float p = 1.f / (1.f + expf(-(acc + b_act[0])));
        g_probs[m] = p;
        out_probs[m] = p;
    }
}

// ============ Kernel 4: ACT halting scan
__global__ void k_halt() {
    extern __shared__ float ps[];
    int tid = threadIdx.x;
    for (int i = tid; i < Bn * Tn; i += 384) {
        int b = i / Tn, t = i - b * Tn;
        ps[b * (Tn + 1) + t] = g_probs[i];
    }
    __syncthreads();
    if (tid < Bn) {
        int b = tid;
        const float* pb = ps + b * (Tn + 1);
        float acc = 0.f;
        int ns = 0;
        for (int t = 0; t < Tn; t++) {
            float p = pb[t];
            float a = acc + p;
            if (a > THRESH) {
                g_weights[b * Tn + t] = p - (a - 1.f);
                g_segend[b * Tn + ns] = t;
                ns++;
                acc = 0.f;
            } else {
                g_weights[b * Tn + t] = p;
                acc = a;
            }
        }
        g_nsegs[b] = ns;
    }
}

// ============ Kernel 5: segment sums -> output embs
__global__ __launch_bounds__(128) void k_out(float* __restrict__ out) {
    int bs = blockIdx.x;
    int b = bs / Tn, s = bs - b * Tn;
    float* o = out + (size_t)bs * Dn;
    int tid = threadIdx.x;
    if (s >= g_nsegs[b]) {
        for (int d = tid; d < Dn; d += 128) o[d] = 0.f;
        return;
    }
    int t1 = g_segend[b * Tn + s];
    int t0 = (s == 0) ? 0 : g_segend[b * Tn + s - 1] + 1;
    for (int d = tid; d < Dn; d += 128) {
        float sum = 0.f;
        for (int t = t0; t <= t1; t++)
            sum += g_states[(size_t)(b * Tn + t) * Dn + d] * g_weights[b * Tn + t];
        o[d] = sum;
    }
}

extern "C" void kernel_launch(void* const* d_in, const int* in_sizes, int n_in,
                              void* d_out, int out_size) {
    const int* sent    = (const int*)d_in[0];
    const float* emb   = (const float*)d_in[1];
    const float* w_ih  = (const float*)d_in[2];
    const float* w_hh  = (const float*)d_in[3];
    const float* b_ih  = (const float*)d_in[4];
    const float* b_hh  = (const float*)d_in[5];
    const float* w_act = (const float*)d_in[6];
    const float* b_act = (const float*)d_in[7];
    float* out = (float*)d_out;

    cudaFuncSetAttribute(k_gru, cudaFuncAttributeMaxDynamicSharedMemorySize, SMEM_GRU);
    cudaFuncSetAttribute(k_halt, cudaFuncAttributeMaxDynamicSharedMemorySize,
                         Bn * (Tn + 1) * 4);

    k_split_x<<<(Bn * Tn * 192) / 256, 256>>>(sent, emb);
    k_split_w<<<(D3 * 192) / 256, 256>>>(w_ih);
    k_prep_w<<<GRP_NB, 256>>>(w_hh);
    k_xp_mma<<<dim3(D3 / 128, (Bn * Tn) / 128), 256>>>(b_ih);
    k_gru<<<NB, 256, SMEM_GRU>>>(b_hh);
    k_probs<<<(Bn * Tn) / 8, 256>>>(w_act, b_act, out + (size_t)Bn * Tn * Dn);
    k_halt<<<1, 384, Bn * (Tn + 1) * 4>>>();
    k_out<<<Bn * Tn, 128>>>(out);
}